// round 12
// baseline (speedup 1.0000x reference)
#include <cuda_runtime.h>
#include <cuda_bf16.h>
#include <math.h>

typedef unsigned int uint32;

// ============================================================================
// HeadGroupedFusionGate, mma.sync bf16 3-term split (x*w ~ xh*wh + xl*wh + xh*wl).
// R12: branch conversion + stats evicted from k_tail into streaming cvt blocks
//      in k_pre (writes pre-swizzled A hi/lo tiles + stat tiles to gmem).
//      k_tail mainloop = bulk-DMA A + B -> ldsm -> mma only. 3 CTAs/SM.
// ============================================================================

__device__ uint4 g_WhV[21 * 1088];        // B: [chunk][k=64][n=136 pad] bf16
__device__ uint4 g_WlV[21 * 1088];
__device__ float g_hidc[2][4096 * 128];
__device__ uint4 g_At[1024 * 4 * 1152];   // A: [block][branch][hi 9216 | lo 9216]
__device__ uint4 g_St[1024 * 384];        // S: [block][hi 3072 | lo 3072]

// ---- PTX helpers ----
__device__ __forceinline__ uint32 smem_u32(const void* p) {
    uint32 a;
    asm("{ .reg .u64 t; cvta.to.shared.u64 t, %1; cvt.u32.u64 %0, t; }" : "=r"(a) : "l"(p));
    return a;
}
__device__ __forceinline__ void ldsm4(uint32* r, uint32 a) {
    asm volatile("ldmatrix.sync.aligned.m8n8.x4.shared.b16 {%0,%1,%2,%3}, [%4];"
        : "=r"(r[0]), "=r"(r[1]), "=r"(r[2]), "=r"(r[3]) : "r"(a));
}
__device__ __forceinline__ void ldsm4t(uint32* r, uint32 a) {
    asm volatile("ldmatrix.sync.aligned.m8n8.x4.trans.shared.b16 {%0,%1,%2,%3}, [%4];"
        : "=r"(r[0]), "=r"(r[1]), "=r"(r[2]), "=r"(r[3]) : "r"(a));
}
__device__ __forceinline__ void mma16816(float* d, const uint32* a, uint32 b0, uint32 b1) {
    asm volatile("mma.sync.aligned.m16n8k16.row.col.f32.bf16.bf16.f32 "
        "{%0,%1,%2,%3}, {%4,%5,%6,%7}, {%8,%9}, {%0,%1,%2,%3};"
        : "+f"(d[0]), "+f"(d[1]), "+f"(d[2]), "+f"(d[3])
        : "r"(a[0]), "r"(a[1]), "r"(a[2]), "r"(a[3]), "r"(b0), "r"(b1));
}
__device__ __forceinline__ void cvtpair(float v0, float v1, uint32& h, uint32& l) {
    __nv_bfloat162 hp = __floats2bfloat162_rn(v0, v1);
    h = *(uint32*)&hp;
    float r0 = v0 - __bfloat162float(hp.x);
    float r1 = v1 - __bfloat162float(hp.y);
    __nv_bfloat162 lp = __floats2bfloat162_rn(r0, r1);
    l = *(uint32*)&lp;
}
#define MBAR_INIT(mb, n) \
    asm volatile("mbarrier.init.shared.b64 [%0], %1;" :: "r"(mb), "r"(n) : "memory")
#define MBAR_EXPECT(mb, tx) \
    asm volatile("mbarrier.arrive.expect_tx.shared.b64 _, [%0], %1;" :: "r"(mb), "r"(tx) : "memory")
__device__ __forceinline__ void bulk_cp(uint32 dst, const void* src, uint32 bytes, uint32 mb) {
    asm volatile("cp.async.bulk.shared::cta.global.mbarrier::complete_tx::bytes "
                 "[%0], [%1], %2, [%3];" :: "r"(dst), "l"(src), "r"(bytes), "r"(mb) : "memory");
}
__device__ __forceinline__ void mbar_wait(uint32 mb, uint32 parity) {
    asm volatile(
        "{\n\t.reg .pred P;\n\t"
        "W%=:\n\tmbarrier.try_wait.parity.acquire.cta.shared::cta.b64 P, [%0], %1, 0x989680;\n\t"
        "@P bra.uni D%=;\n\tbra.uni W%=;\n\tD%=:\n\t}"
        :: "r"(mb), "r"(parity) : "memory");
}

// warp tile 32 rows x 32 cols; NK k16 steps; low-register (one 16-col B half live).
template <int NK, int SA>
__device__ __forceinline__ void mma_chunk(float (&acc)[2][4][4],
                                          uint32 Ah, uint32 Al,
                                          uint32 Bh, uint32 Bl, int lane) {
    uint32 aoff = (uint32)((lane & 15) * SA + (lane >> 4) * 16);
    uint32 boff = (uint32)(((lane & 7) + ((lane >> 3) & 1) * 8) * 272 + ((lane >> 4) & 1) * 16);
#pragma unroll
    for (int k = 0; k < NK; ++k) {
        uint32 ah[2][4], al[2][4];
        ldsm4(ah[0], Ah + aoff + k * 32);
        ldsm4(ah[1], Ah + 16 * SA + aoff + k * 32);
        ldsm4(al[0], Al + aoff + k * 32);
        ldsm4(al[1], Al + 16 * SA + aoff + k * 32);
        uint32 bb = boff + k * 4352;
#pragma unroll
        for (int half = 0; half < 2; ++half) {
            uint32 bh[4], bl[4];
            ldsm4t(bh, Bh + bb + half * 32);
            ldsm4t(bl, Bl + bb + half * 32);
#pragma unroll
            for (int m = 0; m < 2; ++m) {
                mma16816(acc[m][2 * half + 0], ah[m], bh[0], bh[1]);
                mma16816(acc[m][2 * half + 1], ah[m], bh[2], bh[3]);
                mma16816(acc[m][2 * half + 0], al[m], bh[0], bh[1]);
                mma16816(acc[m][2 * half + 1], al[m], bh[2], bh[3]);
                mma16816(acc[m][2 * half + 0], ah[m], bl[0], bl[1]);
                mma16816(acc[m][2 * half + 1], ah[m], bl[2], bl[3]);
            }
        }
    }
}

// ============================================================================
// k_pre: bid 0..127  hidden GEMM | 128..172 tail-weight prep | 173.. branch cvt.
// smem (hid): AHI 0 (9216) | ALO 9216 | BH 18432 (17408) | BL 35840. = 53248.
// ============================================================================
#define P_ALO  9216
#define P_BH   18432
#define P_BL   35840
#define P_SMEM 53248

__global__ void __launch_bounds__(256) k_pre(
    const float* __restrict__ hidden, const float* __restrict__ W1,
    const float* __restrict__ br0, const float* __restrict__ br1,
    const float* __restrict__ br2, const float* __restrict__ br3) {
    int tid = threadIdx.x;
    if (blockIdx.x >= 173) {            // ---- branch cvt + stats path ----
        int b2 = blockIdx.x - 173;      // 0..1023
        int tok0 = b2 * 4;
        char* Abase = (char*)g_At + (size_t)b2 * 4 * 18432;
        char* Sbase = (char*)g_St + (size_t)b2 * 6144;
        if (tid < 64) {                 // stats pad k=12..15
            *(uint2*)(Sbase + tid * 48 + 24) = make_uint2(0u, 0u);
            *(uint2*)(Sbase + 3072 + tid * 48 + 24) = make_uint2(0u, 0u);
        }
        const float* brs[4] = {br0, br1, br2, br3};
#pragma unroll
        for (int p = 0; p < 4; ++p) {
            char* At = Abase + p * 18432;
#pragma unroll
            for (int i = 0; i < 4; ++i) {
                float4 v = ((const float4*)brs[p])[(size_t)tok0 * 256 + tid + 256 * i];
                int row = (tid >> 4) + 16 * i, seg = tid & 15;
                float s = v.x + v.y + v.z + v.w;
                float s2 = fmaf(v.x, v.x, fmaf(v.y, v.y, fmaf(v.z, v.z, v.w * v.w)));
                float mx = fmaxf(fmaxf(v.x, v.y), fmaxf(v.z, v.w));
#pragma unroll
                for (int d = 1; d <= 8; d <<= 1) {
                    s += __shfl_xor_sync(0xffffffffu, s, d);
                    s2 += __shfl_xor_sync(0xffffffffu, s2, d);
                    mx = fmaxf(mx, __shfl_xor_sync(0xffffffffu, mx, d));
                }
                if (seg < 3) {
                    float sval = (seg == 0) ? s * 0.015625f
                               : (seg == 1) ? sqrtf(fmaxf(s2 * 0.015625f, 1e-8f)) : mx;
                    __nv_bfloat16 h = __float2bfloat16_rn(sval);
                    *(__nv_bfloat16*)(Sbase + row * 48 + (p * 3 + seg) * 2) = h;
                    *(__nv_bfloat16*)(Sbase + 3072 + row * 48 + (p * 3 + seg) * 2) =
                        __float2bfloat16_rn(sval - __bfloat162float(h));
                }
                uint32 h0, l0, h1, l1;
                cvtpair(v.x, v.y, h0, l0);
                cvtpair(v.z, v.w, h1, l1);
                *(uint2*)(At + row * 144 + seg * 8) = make_uint2(h0, h1);
                *(uint2*)(At + 9216 + row * 144 + seg * 8) = make_uint2(l0, l1);
            }
        }
        return;
    }
    if (blockIdx.x >= 128) {            // ---- tail-weight prep path ----
        int b2 = blockIdx.x - 128;      // 0..44
        __nv_bfloat16* Wh = (__nv_bfloat16*)g_WhV;
        __nv_bfloat16* Wl = (__nv_bfloat16*)g_WlV;
        if (tid >= 128) return;
        if (b2 < 32) {
            int rr0 = 1024 + b2 * 8;
#pragma unroll
            for (int j = 0; j < 8; ++j) {
                int rr = rr0 + j;
                int row = 1792 + (rr - 1024);
                float v = W1[(size_t)row * 128 + tid];
                __nv_bfloat16 h = __float2bfloat16_rn(v);
                Wh[rr * 136 + tid] = h;
                Wl[rr * 136 + tid] = __float2bfloat16_rn(v - __bfloat162float(h));
            }
        } else if (b2 < 44) {
            int k = b2 - 32;
            int row0 = 1024 + (k / 3) * 192 + (k % 3) * 64;
            float s = 0.f;
#pragma unroll 8
            for (int d = 0; d < 64; ++d) s += W1[(size_t)(row0 + d) * 128 + tid];
            __nv_bfloat16 h = __float2bfloat16_rn(s);
            Wh[(1280 + k) * 136 + tid] = h;
            Wl[(1280 + k) * 136 + tid] = __float2bfloat16_rn(s - __bfloat162float(h));
        } else {
            __nv_bfloat16 z = __float2bfloat16_rn(0.f);
#pragma unroll
            for (int k = 12; k < 16; ++k) {
                Wh[(1280 + k) * 136 + tid] = z;
                Wl[(1280 + k) * 136 + tid] = z;
            }
        }
        return;
    }

    // ---- hidden GEMM path (R11) ----
    extern __shared__ char sm[];
    uint32 sb = smem_u32(sm);
    int lane = tid & 31, w = tid >> 5;
    int rb = (w >> 2) * 32, cb = (w & 3) * 32;
    int tg = blockIdx.x >> 1, khalf = blockIdx.x & 1;
    int tok0 = tg * 64;
    const float4* hidf4 = (const float4*)hidden;
    const float4* W1f4  = (const float4*)W1;

    float acc[2][4][4];
#pragma unroll
    for (int m = 0; m < 2; ++m)
#pragma unroll
        for (int n = 0; n < 4; ++n)
#pragma unroll
            for (int i = 0; i < 4; ++i) acc[m][n][i] = 0.f;

    float4 fa[4], fw[8];
    {
        int c = khalf * 8;
#pragma unroll
        for (int i = 0; i < 4; ++i) {
            int u = tid + 256 * i;
            fa[i] = hidf4[(size_t)(tok0 + (u >> 4)) * 256 + c * 16 + (u & 15)];
        }
#pragma unroll
        for (int i = 0; i < 8; ++i) {
            int u = tid + 256 * i;
            fw[i] = W1f4[(size_t)(c * 64 + (u >> 5)) * 32 + (u & 31)];
        }
    }

    for (int p = 0; p < 8; ++p) {
#pragma unroll
        for (int i = 0; i < 4; ++i) {
            int u = tid + 256 * i;
            int row = u >> 4, seg = u & 15;
            uint32 h0, l0, h1, l1;
            cvtpair(fa[i].x, fa[i].y, h0, l0);
            cvtpair(fa[i].z, fa[i].w, h1, l1);
            *(uint2*)(sm + row * 144 + seg * 8) = make_uint2(h0, h1);
            *(uint2*)(sm + P_ALO + row * 144 + seg * 8) = make_uint2(l0, l1);
        }
#pragma unroll
        for (int i = 0; i < 8; ++i) {
            int u = tid + 256 * i;
            int row = u >> 5, seg = u & 31;
            uint32 h0, l0, h1, l1;
            cvtpair(fw[i].x, fw[i].y, h0, l0);
            cvtpair(fw[i].z, fw[i].w, h1, l1);
            *(uint2*)(sm + P_BH + row * 272 + seg * 8) = make_uint2(h0, h1);
            *(uint2*)(sm + P_BL + row * 272 + seg * 8) = make_uint2(l0, l1);
        }
        if (p < 7) {
            int c = khalf * 8 + p + 1;
#pragma unroll
            for (int i = 0; i < 4; ++i) {
                int u = tid + 256 * i;
                fa[i] = hidf4[(size_t)(tok0 + (u >> 4)) * 256 + c * 16 + (u & 15)];
            }
#pragma unroll
            for (int i = 0; i < 8; ++i) {
                int u = tid + 256 * i;
                fw[i] = W1f4[(size_t)(c * 64 + (u >> 5)) * 32 + (u & 31)];
            }
        }
        __syncthreads();
        uint32 bbase = sb + P_BH + cb * 2;
        mma_chunk<4, 144>(acc, sb + rb * 144, sb + P_ALO + rb * 144,
                          bbase, bbase + 17408, lane);
        __syncthreads();
    }

    float* dst = g_hidc[khalf];
    int q4 = lane >> 2, q = lane & 3;
#pragma unroll
    for (int m = 0; m < 2; ++m)
#pragma unroll
        for (int nt = 0; nt < 4; ++nt) {
            int c0 = cb + nt * 8 + 2 * q;
            int rA = rb + 16 * m + q4;
            *(float2*)&dst[(size_t)(tok0 + rA) * 128 + c0] = make_float2(acc[m][nt][0], acc[m][nt][1]);
            *(float2*)&dst[(size_t)(tok0 + rA + 8) * 128 + c0] = make_float2(acc[m][nt][2], acc[m][nt][3]);
        }
}

// ============================================================================
// k_tail: grid 1024, 256 thr = 8 warps, 3 CTAs/SM. Pure DMA + mma mainloop.
// smem: ABUF 0 (18432: hi|lo) | BBUF 18432 (34816: hi|lo) | AS 53248 (6144)
//       HID 59392 (2048) | W2S 61440 (2048) | SHP 63488 (4096) | MSC 67584 (512)
//       MB 68096 (8). Total 68112.
// ============================================================================
#define T_BB   18432
#define T_AS   53248
#define T_HID  59392
#define T_W2S  61440
#define T_SHP  63488
#define T_MSC  67584
#define T_MB   68096
#define T_SMEM 68112

__global__ void __launch_bounds__(256, 3) k_tail(
    const float* __restrict__ b1, const float* __restrict__ W2,
    const float* __restrict__ b2, const float* __restrict__ epsf,
    const float* __restrict__ temp, float* __restrict__ out) {
    extern __shared__ char sm[];
    uint32 sb = smem_u32(sm);
    int tid = threadIdx.x, lane = tid & 31, w = tid >> 5;
    int rowg = w >> 2, colg = w & 3;
    int rb = rowg * 32, cb = colg * 32;
    int q4 = lane >> 2, q = lane & 3;
    int blk = blockIdx.x;
    int tok0 = blk * 4;
    const char* Ag = (const char*)g_At + (size_t)blk * 4 * 18432;
    const char* Sg = (const char*)g_St + (size_t)blk * 6144;
    const char* WhB = (const char*)g_WhV;
    const char* WlB = (const char*)g_WlV;

    if (tid == 0) {
        MBAR_INIT(sb + T_MB, 1);
        MBAR_EXPECT(sb + T_MB, 53248u);
        bulk_cp(sb, Ag, 18432u, sb + T_MB);
        bulk_cp(sb + T_BB, WhB + (size_t)16 * 17408, 17408u, sb + T_MB);
        bulk_cp(sb + T_BB + 17408, WlB + (size_t)16 * 17408, 17408u, sb + T_MB);
    }
    // prologue staging (overlaps DMA)
    if (tid < 128) {
        int row = tid >> 5, c4 = tid & 31;
        float4 a0 = *(const float4*)&g_hidc[0][(size_t)(tok0 + row) * 128 + c4 * 4];
        float4 a1 = *(const float4*)&g_hidc[1][(size_t)(tok0 + row) * 128 + c4 * 4];
        float4 c = ((const float4*)b1)[c4];
        *(float4*)(sm + T_HID + tid * 16) = make_float4(
            a0.x + a1.x + c.x, a0.y + a1.y + c.y, a0.z + a1.z + c.z, a0.w + a1.w + c.w);
        *(float4*)(sm + T_W2S + tid * 16) = ((const float4*)W2)[tid];
    }
    {
        float* msc = (float*)(sm + T_MSC);
        if (tid < 4)  msc[tid] = b2[tid];
        if (tid < 16) msc[4 + tid] = temp[tid];
        if (tid < 64) msc[20 + tid] = epsf[tid];
    }
    __syncthreads();

    float acc[2][4][4];
#pragma unroll
    for (int m = 0; m < 2; ++m)
#pragma unroll
        for (int n = 0; n < 4; ++n)
#pragma unroll
            for (int i = 0; i < 4; ++i) acc[m][n][i] = 0.f;

    uint32 ph = 0;
    for (int p = 0; p < 5; ++p) {
        mbar_wait(sb + T_MB, ph); ph ^= 1;
        uint32 bbase = sb + T_BB + cb * 2;
        if (p < 4)
            mma_chunk<4, 144>(acc, sb + rb * 144, sb + 9216 + rb * 144,
                              bbase, bbase + 17408, lane);
        else
            mma_chunk<1, 48>(acc, sb + T_AS + rb * 48, sb + T_AS + 3072 + rb * 48,
                             bbase, bbase + 17408, lane);
        __syncthreads();                   // all warps done with buffers
        if (p < 4 && tid == 0) {
            if (p < 3) {
                MBAR_EXPECT(sb + T_MB, 53248u);
                bulk_cp(sb, Ag + (size_t)(p + 1) * 18432, 18432u, sb + T_MB);
                bulk_cp(sb + T_BB, WhB + (size_t)(17 + p) * 17408, 17408u, sb + T_MB);
                bulk_cp(sb + T_BB + 17408, WlB + (size_t)(17 + p) * 17408, 17408u, sb + T_MB);
            } else {
                MBAR_EXPECT(sb + T_MB, 14848u);
                bulk_cp(sb + T_AS, Sg, 6144u, sb + T_MB);
                bulk_cp(sb + T_BB, WhB + (size_t)20 * 17408, 4352u, sb + T_MB);
                bulk_cp(sb + T_BB + 17408, WlB + (size_t)20 * 17408, 4352u, sb + T_MB);
            }
        }
    }

    // ---- epilogue: gelu + W2 partial logits ----
    float lg[4][4];
#pragma unroll
    for (int s = 0; s < 4; ++s)
#pragma unroll
        for (int j = 0; j < 4; ++j) lg[s][j] = 0.f;
#pragma unroll
    for (int m = 0; m < 2; ++m) {
        int tokc = rowg * 2 + m;
#pragma unroll
        for (int nt = 0; nt < 4; ++nt) {
            int c0 = cb + nt * 8 + 2 * q;
            float2 hv = *(const float2*)(sm + T_HID + (tokc * 128 + c0) * 4);
            float4 wa = *(const float4*)(sm + T_W2S + c0 * 16);
            float4 wb = *(const float4*)(sm + T_W2S + (c0 + 1) * 16);
            float v0 = acc[m][nt][0] + hv.x, v1 = acc[m][nt][1] + hv.y;
            float v2 = acc[m][nt][2] + hv.x, v3 = acc[m][nt][3] + hv.y;
            float g0 = v0 * normcdff(v0), g1 = v1 * normcdff(v1);
            float g2 = v2 * normcdff(v2), g3 = v3 * normcdff(v3);
            lg[2 * m][0] = fmaf(g0, wa.x, fmaf(g1, wb.x, lg[2 * m][0]));
            lg[2 * m][1] = fmaf(g0, wa.y, fmaf(g1, wb.y, lg[2 * m][1]));
            lg[2 * m][2] = fmaf(g0, wa.z, fmaf(g1, wb.z, lg[2 * m][2]));
            lg[2 * m][3] = fmaf(g0, wa.w, fmaf(g1, wb.w, lg[2 * m][3]));
            lg[2 * m + 1][0] = fmaf(g2, wa.x, fmaf(g3, wb.x, lg[2 * m + 1][0]));
            lg[2 * m + 1][1] = fmaf(g2, wa.y, fmaf(g3, wb.y, lg[2 * m + 1][1]));
            lg[2 * m + 1][2] = fmaf(g2, wa.z, fmaf(g3, wb.z, lg[2 * m + 1][2]));
            lg[2 * m + 1][3] = fmaf(g2, wa.w, fmaf(g3, wb.w, lg[2 * m + 1][3]));
        }
    }
#pragma unroll
    for (int d = 1; d <= 2; d <<= 1)
#pragma unroll
        for (int s = 0; s < 4; ++s)
#pragma unroll
            for (int j = 0; j < 4; ++j)
                lg[s][j] += __shfl_xor_sync(0xffffffffu, lg[s][j], d);
    if (q == 0) {
#pragma unroll
        for (int s = 0; s < 4; ++s)
            *(float4*)(sm + T_SHP + (colg * 64 + rb + q4 + 8 * s) * 16) =
                make_float4(lg[s][0], lg[s][1], lg[s][2], lg[s][3]);
    }
    __syncthreads();

    if (tid < 64) {
        const float* msc = (const float*)(sm + T_MSC);
        int h = tid & 15;
        float l0 = msc[0], l1 = msc[1], l2 = msc[2], l3 = msc[3];
#pragma unroll
        for (int cg = 0; cg < 4; ++cg) {
            float4 pp = *(const float4*)(sm + T_SHP + (cg * 64 + tid) * 16);
            l0 += pp.x; l1 += pp.y; l2 += pp.z; l3 += pp.w;
        }
        float tt = fminf(fmaxf(msc[4 + h], 0.2f), 10.f);
        float it = 1.f / tt;
        float m = fmaxf(fmaxf(l0, l1), fmaxf(l2, l3));
        float e0 = expf((l0 - m) * it), e1 = expf((l1 - m) * it);
        float e2 = expf((l2 - m) * it), e3 = expf((l3 - m) * it);
        float inv = 1.f / (e0 + e1 + e2 + e3);
        float q0 = e0 * inv, q1 = e1 * inv, q2 = e2 * inv, q3 = e3 * inv;
        q0 = fmaxf(q0, fminf(fmaxf(msc[20 + h * 4 + 0], 1e-7f), 0.1f));
        q1 = fmaxf(q1, fminf(fmaxf(msc[20 + h * 4 + 1], 1e-7f), 0.1f));
        q2 = fmaxf(q2, fminf(fmaxf(msc[20 + h * 4 + 2], 1e-7f), 0.1f));
        q3 = fmaxf(q3, fminf(fmaxf(msc[20 + h * 4 + 3], 1e-7f), 0.1f));
        inv = 1.f / (q0 + q1 + q2 + q3);
        *(float4*)&out[(size_t)(tok0 * 16 + tid) * 4] =
            make_float4(q0 * inv, q1 * inv, q2 * inv, q3 * inv);
    }
}

extern "C" void kernel_launch(void* const* d_in, const int* in_sizes, int n_in,
                              void* d_out, int out_size) {
    const float* hidden = (const float*)d_in[0];
    const float* br0    = (const float*)d_in[1];
    const float* br1    = (const float*)d_in[2];
    const float* br2    = (const float*)d_in[3];
    const float* br3    = (const float*)d_in[4];
    const float* W1     = (const float*)d_in[5];
    const float* b1     = (const float*)d_in[6];
    const float* W2     = (const float*)d_in[7];
    const float* b2     = (const float*)d_in[8];
    const float* epsf   = (const float*)d_in[9];
    const float* temp   = (const float*)d_in[10];
    float* out = (float*)d_out;

    cudaFuncSetAttribute(k_pre,  cudaFuncAttributeMaxDynamicSharedMemorySize, P_SMEM);
    cudaFuncSetAttribute(k_tail, cudaFuncAttributeMaxDynamicSharedMemorySize, T_SMEM);

    k_pre<<<1197, 256, P_SMEM>>>(hidden, W1, br0, br1, br2, br3);
    k_tail<<<1024, 256, T_SMEM>>>(b1, W2, b2, epsf, temp, out);
}